// round 5
// baseline (speedup 1.0000x reference)
#include <cuda_runtime.h>
#include <math.h>

#define BB 2
#define SS 2048
#define EE 1024
#define HH 16
#define HD 64
#define MTOT (BB*SS)
#define SCALE 0.125f   // 1/sqrt(64)

// Scratch (allocation-free rule): device globals
__device__ float g_q[MTOT * EE];
__device__ float g_k[MTOT * EE];
__device__ float g_v[MTOT * EE];
__device__ float g_att[MTOT * EE];

// ---------------------------------------------------------------------------
// tf32 helpers
// ---------------------------------------------------------------------------
__device__ __forceinline__ unsigned f2tf(float f) {
    unsigned r;
    asm("cvt.rna.tf32.f32 %0, %1;" : "=r"(r) : "f"(f));
    return r;
}

__device__ __forceinline__ void mma_tf32(float c[4], const unsigned a[4], const unsigned b[2]) {
    asm volatile(
        "mma.sync.aligned.m16n8k8.row.col.f32.tf32.tf32.f32 "
        "{%0,%1,%2,%3}, {%4,%5,%6,%7}, {%8,%9}, {%0,%1,%2,%3};"
        : "+f"(c[0]), "+f"(c[1]), "+f"(c[2]), "+f"(c[3])
        : "r"(a[0]), "r"(a[1]), "r"(a[2]), "r"(a[3]), "r"(b[0]), "r"(b[1]));
}

// ---------------------------------------------------------------------------
// GEMM: C[M,N] = A[M,K] @ W[N,K]^T + bias   (M=4096, N=K=1024)
// CTA 128x128x16, 256 threads (8 warps: 2 in M x 4 in N), warp tile 64x32.
// BK=16 halves staging registers vs R2 -> fits 2 CTAs/SM (16 warps).
// smem row stride 20 words: fragment-read banks (20g+t) mod 32 all distinct.
// Register-staged double buffering, one __syncthreads per K-iter.
// ---------------------------------------------------------------------------
#define GSTR 20
#define STG_W (128 * GSTR * 2)   // 5120 words per stage (A then B)

struct QKVArgs {
    const float* A[3];
    const float* W[3];
    const float* bias[3];
    float*       C[3];
};

__device__ __forceinline__ void gemm_body(
    const float* __restrict__ A, const float* __restrict__ W,
    const float* __restrict__ bias, float* __restrict__ C)
{
    extern __shared__ unsigned sm[];   // 2 stages x 5120 words = 40 KB

    const int tid  = threadIdx.x;
    const int warp = tid >> 5, lane = tid & 31;
    const int g = lane >> 2, t = lane & 3;
    const int wm = warp & 1, wn = warp >> 1;     // 2 x 4 warps, warp tile 64x32
    const int bm = blockIdx.y * 128, bn = blockIdx.x * 128;

    // staging: thread handles rows m0 and m0+64, k-quad kq0 (16 floats / tile / operand)
    const int m0  = tid >> 2;        // 0..63
    const int kq0 = tid & 3;         // 0..3
    const float* Arow = A + (size_t)(bm + m0) * EE + kq0 * 4;
    const float* Wrow = W + (size_t)(bn + m0) * EE + kq0 * 4;
    const int woff = m0 * GSTR + kq0 * 4;

    float4 ra[2], rb[2];
    float acc[4][4][4] = {};

    // preload tile 0
    ra[0] = *(const float4*)(Arow);
    ra[1] = *(const float4*)(Arow + (size_t)64 * EE);
    rb[0] = *(const float4*)(Wrow);
    rb[1] = *(const float4*)(Wrow + (size_t)64 * EE);
    // commit tile 0 -> stage 0
    {
        unsigned* pa = sm + woff;
        pa[0] = f2tf(ra[0].x); pa[1] = f2tf(ra[0].y); pa[2] = f2tf(ra[0].z); pa[3] = f2tf(ra[0].w);
        unsigned* pa1 = sm + woff + 64 * GSTR;
        pa1[0] = f2tf(ra[1].x); pa1[1] = f2tf(ra[1].y); pa1[2] = f2tf(ra[1].z); pa1[3] = f2tf(ra[1].w);
        unsigned* pb = sm + 128 * GSTR + woff;
        pb[0] = f2tf(rb[0].x); pb[1] = f2tf(rb[0].y); pb[2] = f2tf(rb[0].z); pb[3] = f2tf(rb[0].w);
        unsigned* pb1 = sm + 128 * GSTR + woff + 64 * GSTR;
        pb1[0] = f2tf(rb[1].x); pb1[1] = f2tf(rb[1].y); pb1[2] = f2tf(rb[1].z); pb1[3] = f2tf(rb[1].w);
    }
    __syncthreads();
    // preload tile 1
    ra[0] = *(const float4*)(Arow + 16);
    ra[1] = *(const float4*)(Arow + (size_t)64 * EE + 16);
    rb[0] = *(const float4*)(Wrow + 16);
    rb[1] = *(const float4*)(Wrow + (size_t)64 * EE + 16);

    const int NK = EE / 16;   // 64
    for (int kt = 0; kt < NK; kt++) {
        const unsigned* Asm = sm + (kt & 1) * STG_W;
        const unsigned* Bsm = Asm + 128 * GSTR;

        // ---- compute 2 k-steps of 8
        #pragma unroll
        for (int ksc = 0; ksc < 2; ksc++) {
            unsigned af[4][4], bf[4][2];
            #pragma unroll
            for (int mi = 0; mi < 4; mi++) {
                const int row = wm * 64 + mi * 16;
                af[mi][0] = Asm[(row + g)     * GSTR + ksc * 8 + t];
                af[mi][1] = Asm[(row + g + 8) * GSTR + ksc * 8 + t];
                af[mi][2] = Asm[(row + g)     * GSTR + ksc * 8 + t + 4];
                af[mi][3] = Asm[(row + g + 8) * GSTR + ksc * 8 + t + 4];
            }
            #pragma unroll
            for (int ni = 0; ni < 4; ni++) {
                const int col = wn * 32 + ni * 8 + g;
                bf[ni][0] = Bsm[col * GSTR + ksc * 8 + t];
                bf[ni][1] = Bsm[col * GSTR + ksc * 8 + t + 4];
            }
            #pragma unroll
            for (int mi = 0; mi < 4; mi++)
                #pragma unroll
                for (int ni = 0; ni < 4; ni++)
                    mma_tf32(acc[mi][ni], af[mi], bf[ni]);
        }

        if (kt + 1 < NK) {
            // commit tile kt+1 into the other stage
            unsigned* buf = sm + ((kt + 1) & 1) * STG_W;
            unsigned* pa = buf + woff;
            pa[0] = f2tf(ra[0].x); pa[1] = f2tf(ra[0].y); pa[2] = f2tf(ra[0].z); pa[3] = f2tf(ra[0].w);
            unsigned* pa1 = buf + woff + 64 * GSTR;
            pa1[0] = f2tf(ra[1].x); pa1[1] = f2tf(ra[1].y); pa1[2] = f2tf(ra[1].z); pa1[3] = f2tf(ra[1].w);
            unsigned* pb = buf + 128 * GSTR + woff;
            pb[0] = f2tf(rb[0].x); pb[1] = f2tf(rb[0].y); pb[2] = f2tf(rb[0].z); pb[3] = f2tf(rb[0].w);
            unsigned* pb1 = buf + 128 * GSTR + woff + 64 * GSTR;
            pb1[0] = f2tf(rb[1].x); pb1[1] = f2tf(rb[1].y); pb1[2] = f2tf(rb[1].z); pb1[3] = f2tf(rb[1].w);
            __syncthreads();
            if (kt + 2 < NK) {
                const float* a2 = Arow + (kt + 2) * 16;
                const float* w2 = Wrow + (kt + 2) * 16;
                ra[0] = *(const float4*)(a2);
                ra[1] = *(const float4*)(a2 + (size_t)64 * EE);
                rb[0] = *(const float4*)(w2);
                rb[1] = *(const float4*)(w2 + (size_t)64 * EE);
            }
        }
    }

    // ---- epilogue: add bias, store
    #pragma unroll
    for (int mi = 0; mi < 4; mi++) {
        #pragma unroll
        for (int r2 = 0; r2 < 2; r2++) {
            const int m = bm + wm * 64 + mi * 16 + g + r2 * 8;
            #pragma unroll
            for (int ni = 0; ni < 4; ni++) {
                const int n = bn + wn * 32 + ni * 8 + 2 * t;
                float2 bv = *(const float2*)(bias + n);
                float2 o;
                o.x = acc[mi][ni][r2 * 2 + 0] + bv.x;
                o.y = acc[mi][ni][r2 * 2 + 1] + bv.y;
                *(float2*)(C + (size_t)m * EE + n) = o;
            }
        }
    }
}

__global__ __launch_bounds__(256, 2) void qkv_gemm(QKVArgs args) {
    const int z = blockIdx.z;
    gemm_body(args.A[z], args.W[z], args.bias[z], args.C[z]);
}

__global__ __launch_bounds__(256, 2) void out_gemm(const float* __restrict__ A,
                                                   const float* __restrict__ W,
                                                   const float* __restrict__ bias,
                                                   float* __restrict__ C) {
    gemm_body(A, W, bias, C);
}

// ---------------------------------------------------------------------------
// Flash attention with tf32 mma (R2-proven, unchanged).
// Block = (b, h, 64 q-rows), 128 threads (4 warps, 16 rows each).
// Q kept as tf32 A-fragments in registers. smem stride 68 (68 % 32 == 4).
// ---------------------------------------------------------------------------
#define ASTR 68

__global__ __launch_bounds__(128) void attn_tc() {
    extern __shared__ unsigned smem[];
    unsigned* Ks = smem;                // 64*68
    unsigned* Vs = smem + 64 * ASTR;    // 64*68
    unsigned* Ps = smem + 2 * 64 * ASTR;// 64*68 (Q staging, then P tiles)

    const int tid  = threadIdx.x;
    const int warp = tid >> 5, lane = tid & 31;
    const int g = lane >> 2, t = lane & 3;
    const int bh = blockIdx.x;
    const int b = bh >> 4, h = bh & 15;
    const int q0 = blockIdx.y * 64;

    const size_t base = (size_t)b * SS * EE + (size_t)h * HD;

    // ---- stage Q (scaled, tf32) through Ps, then pull A-fragments to regs
    {
        const float* qp = g_q + base + (size_t)q0 * EE;
        #pragma unroll
        for (int i = 0; i < 8; i++) {
            int id = tid + i * 128;           // 1024 float4: 64 rows x 16
            int r = id >> 4, c4 = id & 15;
            float4 v = *(const float4*)(qp + (size_t)r * EE + c4 * 4);
            unsigned* p = &Ps[r * ASTR + c4 * 4];
            p[0] = f2tf(v.x * SCALE); p[1] = f2tf(v.y * SCALE);
            p[2] = f2tf(v.z * SCALE); p[3] = f2tf(v.w * SCALE);
        }
    }
    __syncthreads();

    unsigned qf[8][4];
    {
        int m = warp * 16;
        #pragma unroll
        for (int ks = 0; ks < 8; ks++) {
            qf[ks][0] = Ps[(m + g)     * ASTR + ks * 8 + t];
            qf[ks][1] = Ps[(m + g + 8) * ASTR + ks * 8 + t];
            qf[ks][2] = Ps[(m + g)     * ASTR + ks * 8 + t + 4];
            qf[ks][3] = Ps[(m + g + 8) * ASTR + ks * 8 + t + 4];
        }
    }
    __syncthreads();

    float o[8][4] = {};
    float mrow0 = -1e30f, mrow1 = -1e30f, lrow0 = 0.f, lrow1 = 0.f;

    const float* kp = g_k + base;
    const float* vp = g_v + base;

    for (int kt = 0; kt < SS / 64; kt++) {
        // ---- load K,V tiles (tf32)
        #pragma unroll
        for (int i = 0; i < 8; i++) {
            int id = tid + i * 128; int r = id >> 4, c4 = id & 15;
            size_t go = (size_t)(kt * 64 + r) * EE + c4 * 4;
            float4 kv = *(const float4*)(kp + go);
            float4 vv = *(const float4*)(vp + go);
            unsigned* pk = &Ks[r * ASTR + c4 * 4];
            pk[0] = f2tf(kv.x); pk[1] = f2tf(kv.y); pk[2] = f2tf(kv.z); pk[3] = f2tf(kv.w);
            unsigned* pv = &Vs[r * ASTR + c4 * 4];
            pv[0] = f2tf(vv.x); pv[1] = f2tf(vv.y); pv[2] = f2tf(vv.z); pv[3] = f2tf(vv.w);
        }
        __syncthreads();

        // ---- S = Q @ K^T  (per warp: 16 x 64)
        float s[8][4] = {};
        #pragma unroll
        for (int ks = 0; ks < 8; ks++) {
            #pragma unroll
            for (int ni = 0; ni < 8; ni++) {
                unsigned bf[2];
                int n = ni * 8 + g;                       // kv index
                bf[0] = Ks[n * ASTR + ks * 8 + t];
                bf[1] = Ks[n * ASTR + ks * 8 + t + 4];
                mma_tf32(s[ni], qf[ks], bf);
            }
        }

        // ---- online softmax (rows g and g+8; reduce over the 4 lanes of t)
        float mx0 = -1e30f, mx1 = -1e30f;
        #pragma unroll
        for (int ni = 0; ni < 8; ni++) {
            mx0 = fmaxf(mx0, fmaxf(s[ni][0], s[ni][1]));
            mx1 = fmaxf(mx1, fmaxf(s[ni][2], s[ni][3]));
        }
        mx0 = fmaxf(mx0, __shfl_xor_sync(0xffffffffu, mx0, 1));
        mx0 = fmaxf(mx0, __shfl_xor_sync(0xffffffffu, mx0, 2));
        mx1 = fmaxf(mx1, __shfl_xor_sync(0xffffffffu, mx1, 1));
        mx1 = fmaxf(mx1, __shfl_xor_sync(0xffffffffu, mx1, 2));

        float mn0 = fmaxf(mrow0, mx0), mn1 = fmaxf(mrow1, mx1);
        float c0 = __expf(mrow0 - mn0), c1 = __expf(mrow1 - mn1);
        float sum0 = 0.f, sum1 = 0.f;
        #pragma unroll
        for (int ni = 0; ni < 8; ni++) {
            s[ni][0] = __expf(s[ni][0] - mn0);
            s[ni][1] = __expf(s[ni][1] - mn0);
            s[ni][2] = __expf(s[ni][2] - mn1);
            s[ni][3] = __expf(s[ni][3] - mn1);
            sum0 += s[ni][0] + s[ni][1];
            sum1 += s[ni][2] + s[ni][3];
        }
        sum0 += __shfl_xor_sync(0xffffffffu, sum0, 1);
        sum0 += __shfl_xor_sync(0xffffffffu, sum0, 2);
        sum1 += __shfl_xor_sync(0xffffffffu, sum1, 1);
        sum1 += __shfl_xor_sync(0xffffffffu, sum1, 2);
        lrow0 = lrow0 * c0 + sum0;  mrow0 = mn0;
        lrow1 = lrow1 * c1 + sum1;  mrow1 = mn1;
        #pragma unroll
        for (int ni = 0; ni < 8; ni++) {
            o[ni][0] *= c0; o[ni][1] *= c0;
            o[ni][2] *= c1; o[ni][3] *= c1;
        }

        // ---- write P (tf32) to warp-local rows of Ps
        {
            int m = warp * 16;
            #pragma unroll
            for (int ni = 0; ni < 8; ni++) {
                uint2 w0 = make_uint2(f2tf(s[ni][0]), f2tf(s[ni][1]));
                uint2 w1 = make_uint2(f2tf(s[ni][2]), f2tf(s[ni][3]));
                *(uint2*)&Ps[(m + g)     * ASTR + ni * 8 + 2 * t] = w0;
                *(uint2*)&Ps[(m + g + 8) * ASTR + ni * 8 + 2 * t] = w1;
            }
        }
        __syncwarp();

        // ---- O += P @ V  (A from Ps, B = Vs[j][d])
        {
            int m = warp * 16;
            #pragma unroll
            for (int ks = 0; ks < 8; ks++) {
                unsigned af[4];
                af[0] = Ps[(m + g)     * ASTR + ks * 8 + t];
                af[1] = Ps[(m + g + 8) * ASTR + ks * 8 + t];
                af[2] = Ps[(m + g)     * ASTR + ks * 8 + t + 4];
                af[3] = Ps[(m + g + 8) * ASTR + ks * 8 + t + 4];
                #pragma unroll
                for (int ni = 0; ni < 8; ni++) {
                    unsigned bf[2];
                    int n = ni * 8 + g;                   // d index
                    bf[0] = Vs[(ks * 8 + t)     * ASTR + n];
                    bf[1] = Vs[(ks * 8 + t + 4) * ASTR + n];
                    mma_tf32(o[ni], af, bf);
                }
            }
        }
        __syncthreads();   // Vs/Ks consumed before next tile load
    }

    // ---- normalize, store
    float inv0 = 1.f / lrow0, inv1 = 1.f / lrow1;
    int r0 = q0 + warp * 16 + g;
    #pragma unroll
    for (int ni = 0; ni < 8; ni++) {
        int d = h * HD + ni * 8 + 2 * t;
        float2 w0 = make_float2(o[ni][0] * inv0, o[ni][1] * inv0);
        float2 w1 = make_float2(o[ni][2] * inv1, o[ni][3] * inv1);
        *(float2*)(g_att + (size_t)(b * SS + r0)     * EE + d) = w0;
        *(float2*)(g_att + (size_t)(b * SS + r0 + 8) * EE + d) = w1;
    }
}

// ---------------------------------------------------------------------------
// Launch
// ---------------------------------------------------------------------------
extern "C" void kernel_launch(void* const* d_in, const int* in_sizes, int n_in,
                              void* d_out, int out_size)
{
    const float* query = (const float*)d_in[0];
    const float* key_  = (const float*)d_in[1];
    const float* value = (const float*)d_in[2];
    const float* Wq = (const float*)d_in[3];
    const float* bq = (const float*)d_in[4];
    const float* Wk = (const float*)d_in[5];
    const float* bk = (const float*)d_in[6];
    const float* Wv = (const float*)d_in[7];
    const float* bv = (const float*)d_in[8];
    const float* Wo = (const float*)d_in[9];
    const float* bo = (const float*)d_in[10];
    float* out = (float*)d_out;

    float *q, *k, *v, *att;
    cudaGetSymbolAddress((void**)&q,   g_q);
    cudaGetSymbolAddress((void**)&k,   g_k);
    cudaGetSymbolAddress((void**)&v,   g_v);
    cudaGetSymbolAddress((void**)&att, g_att);

    static bool attr_done = false;
    if (!attr_done) {
        cudaFuncSetAttribute(qkv_gemm, cudaFuncAttributeMaxDynamicSharedMemorySize, 2 * STG_W * 4);
        cudaFuncSetAttribute(out_gemm, cudaFuncAttributeMaxDynamicSharedMemorySize, 2 * STG_W * 4);
        cudaFuncSetAttribute(attn_tc,  cudaFuncAttributeMaxDynamicSharedMemorySize, 3 * 64 * ASTR * 4);
        attr_done = true;
    }

    QKVArgs args;
    args.A[0] = query; args.A[1] = key_; args.A[2] = value;
    args.W[0] = Wq;    args.W[1] = Wk;   args.W[2] = Wv;
    args.bias[0] = bq; args.bias[1] = bk; args.bias[2] = bv;
    args.C[0] = q;     args.C[1] = k;    args.C[2] = v;

    dim3 gqkv(EE / 128, MTOT / 128, 3);
    qkv_gemm<<<gqkv, 256, 2 * STG_W * 4>>>(args);

    attn_tc<<<dim3(BB * HH, SS / 64), 128, 3 * 64 * ASTR * 4>>>();

    dim3 go(EE / 128, MTOT / 128);
    out_gemm<<<go, 256, 2 * STG_W * 4>>>(att, Wo, bo, out);
}

// round 6
// speedup vs baseline: 1.6884x; 1.6884x over previous
#include <cuda_runtime.h>
#include <math.h>

#define BB 2
#define SS 2048
#define EE 1024
#define HH 16
#define HD 64
#define MTOT (BB*SS)
#define SCALE 0.125f   // 1/sqrt(64)

// Scratch (allocation-free rule): device globals
__device__ float g_q[MTOT * EE];     // tf32-rounded Q projection
__device__ float g_k[MTOT * EE];
__device__ float g_v[MTOT * EE];
__device__ float g_att[MTOT * EE];   // tf32-rounded attention output
__device__ float g_xq[MTOT * EE];    // tf32-rounded inputs
__device__ float g_xk[MTOT * EE];
__device__ float g_xv[MTOT * EE];
__device__ float g_wq[EE * EE];      // tf32-rounded weights
__device__ float g_wk[EE * EE];
__device__ float g_wv[EE * EE];
__device__ float g_wo[EE * EE];

// ---------------------------------------------------------------------------
// helpers
// ---------------------------------------------------------------------------
__device__ __forceinline__ unsigned f2tf(float f) {
    unsigned r;
    asm("cvt.rna.tf32.f32 %0, %1;" : "=r"(r) : "f"(f));
    return r;
}

__device__ __forceinline__ void mma_tf32(float c[4], const unsigned a[4], const unsigned b[2]) {
    asm volatile(
        "mma.sync.aligned.m16n8k8.row.col.f32.tf32.tf32.f32 "
        "{%0,%1,%2,%3}, {%4,%5,%6,%7}, {%8,%9}, {%0,%1,%2,%3};"
        : "+f"(c[0]), "+f"(c[1]), "+f"(c[2]), "+f"(c[3])
        : "r"(a[0]), "r"(a[1]), "r"(a[2]), "r"(a[3]), "r"(b[0]), "r"(b[1]));
}

__device__ __forceinline__ void cpa16(unsigned dst, const void* src) {
    asm volatile("cp.async.cg.shared.global [%0], [%1], 16;" :: "r"(dst), "l"(src) : "memory");
}
__device__ __forceinline__ void cp_commit() { asm volatile("cp.async.commit_group;" ::: "memory"); }
__device__ __forceinline__ void cp_wait0() { asm volatile("cp.async.wait_group 0;" ::: "memory"); }
__device__ __forceinline__ void cp_wait1() { asm volatile("cp.async.wait_group 1;" ::: "memory"); }

// ---------------------------------------------------------------------------
// Prepass: round 7 tensors to tf32 copies
// ---------------------------------------------------------------------------
struct RoundArgs {
    const float* src[7];
    float*       dst[7];
    int          n4[7];
};

__global__ __launch_bounds__(256) void tf32_round(RoundArgs a) {
    const int z = blockIdx.y;
    const int n4 = a.n4[z];
    const float4* s = (const float4*)a.src[z];
    float4* d = (float4*)a.dst[z];
    for (int i = blockIdx.x * blockDim.x + threadIdx.x; i < n4;
         i += gridDim.x * blockDim.x) {
        float4 v = s[i];
        v.x = __uint_as_float(f2tf(v.x));
        v.y = __uint_as_float(f2tf(v.y));
        v.z = __uint_as_float(f2tf(v.z));
        v.w = __uint_as_float(f2tf(v.w));
        d[i] = v;
    }
}

// ---------------------------------------------------------------------------
// GEMM: C[M,N] = A[M,K] @ W[N,K]^T + bias   (A, W pre-rounded tf32)
// R2's exact compute loop: CTA 128x128x32, 256 threads (8 warps 2Mx4N),
// warp tile 64x32, GSTR=36 (conflict-free fragment reads).
// Staging via cp.async, 3 stages, one __syncthreads per K-iter.
// ---------------------------------------------------------------------------
#define GSTR 36
#define STGW 9216            // words per stage: A 128*36, B 128*36
#define STGB (STGW * 4)      // bytes per stage

struct QKVArgs {
    const float* A[3];
    const float* W[3];
    const float* bias[3];
    float*       C[3];
};

template<bool RND>
__device__ __forceinline__ void gemm_body(
    const float* __restrict__ A, const float* __restrict__ W,
    const float* __restrict__ bias, float* __restrict__ C)
{
    extern __shared__ unsigned sm[];   // 3 stages x 9216 words = 108 KB
    const unsigned smem_u = (unsigned)__cvta_generic_to_shared(sm);

    const int tid  = threadIdx.x;
    const int warp = tid >> 5, lane = tid & 31;
    const int g = lane >> 2, t = lane & 3;
    const int wm = warp & 1, wn = warp >> 1;     // 2 x 4 warps, warp tile 64x32
    const int bm = blockIdx.y * 128, bn = blockIdx.x * 128;

    // staging constants: thread covers rows m0+32i (i=0..3), k-quad kq (16B)
    const int kq = tid & 7;          // fixed k-quad
    const int m0 = tid >> 3;         // 0..31
    const float* Asrc = A + (size_t)(bm + m0) * EE + kq * 4;
    const float* Wsrc = W + (size_t)(bn + m0) * EE + kq * 4;
    const unsigned dA = smem_u + (m0 * GSTR + kq * 4) * 4;  // + i*4608B + stage*STGB
    const unsigned dB = dA + 4608 * 4;                      // B block at word 4608

    float acc[4][4][4] = {};
    const int NK = EE / 32;          // 32

    // prologue: stage tiles 0 and 1
    #pragma unroll
    for (int p = 0; p < 2; p++) {
        const unsigned so = p * STGB;
        const int ko = p * 32;
        #pragma unroll
        for (int i = 0; i < 4; i++) {
            cpa16(dA + so + i * 4608, Asrc + ko + (size_t)i * 32 * EE);
            cpa16(dB + so + i * 4608, Wsrc + ko + (size_t)i * 32 * EE);
        }
        cp_commit();
    }

    int st = 0;   // stage holding tile kt
    for (int kt = 0; kt < NK; kt++) {
        if (kt + 1 < NK) cp_wait1(); else cp_wait0();
        __syncthreads();

        // prefetch tile kt+2 into stage (st+2)%3 (its readers done at kt-1)
        if (kt + 2 < NK) {
            const int s2 = (st + 2 >= 3) ? st - 1 : st + 2;
            const unsigned so = s2 * STGB;
            const int ko = (kt + 2) * 32;
            #pragma unroll
            for (int i = 0; i < 4; i++) {
                cpa16(dA + so + i * 4608, Asrc + ko + (size_t)i * 32 * EE);
                cpa16(dB + so + i * 4608, Wsrc + ko + (size_t)i * 32 * EE);
            }
            cp_commit();
        }

        // ---- R2 compute loop: 4 k-steps of 8
        const unsigned* Asm = sm + st * STGW;
        const unsigned* Bsm = Asm + 4608;
        #pragma unroll
        for (int ksc = 0; ksc < 4; ksc++) {
            unsigned af[4][4], bf[4][2];
            #pragma unroll
            for (int mi = 0; mi < 4; mi++) {
                const int row = wm * 64 + mi * 16;
                af[mi][0] = Asm[(row + g)     * GSTR + ksc * 8 + t];
                af[mi][1] = Asm[(row + g + 8) * GSTR + ksc * 8 + t];
                af[mi][2] = Asm[(row + g)     * GSTR + ksc * 8 + t + 4];
                af[mi][3] = Asm[(row + g + 8) * GSTR + ksc * 8 + t + 4];
            }
            #pragma unroll
            for (int ni = 0; ni < 4; ni++) {
                const int col = wn * 32 + ni * 8 + g;
                bf[ni][0] = Bsm[col * GSTR + ksc * 8 + t];
                bf[ni][1] = Bsm[col * GSTR + ksc * 8 + t + 4];
            }
            #pragma unroll
            for (int mi = 0; mi < 4; mi++)
                #pragma unroll
                for (int ni = 0; ni < 4; ni++)
                    mma_tf32(acc[mi][ni], af[mi], bf[ni]);
        }
        st = (st + 1 >= 3) ? 0 : st + 1;
    }

    // ---- epilogue: add bias (fp32), optional tf32 round, store
    #pragma unroll
    for (int mi = 0; mi < 4; mi++) {
        #pragma unroll
        for (int r2 = 0; r2 < 2; r2++) {
            const int m = bm + wm * 64 + mi * 16 + g + r2 * 8;
            #pragma unroll
            for (int ni = 0; ni < 4; ni++) {
                const int n = bn + wn * 32 + ni * 8 + 2 * t;
                float2 bv = *(const float2*)(bias + n);
                float2 o;
                o.x = acc[mi][ni][r2 * 2 + 0] + bv.x;
                o.y = acc[mi][ni][r2 * 2 + 1] + bv.y;
                if (RND) {
                    o.x = __uint_as_float(f2tf(o.x));
                    o.y = __uint_as_float(f2tf(o.y));
                }
                *(float2*)(C + (size_t)m * EE + n) = o;
            }
        }
    }
}

__global__ __launch_bounds__(256, 2) void qkv_gemm(QKVArgs args) {
    const int z = blockIdx.z;
    gemm_body<true>(args.A[z], args.W[z], args.bias[z], args.C[z]);
}

__global__ __launch_bounds__(256, 2) void out_gemm(const float* __restrict__ A,
                                                   const float* __restrict__ W,
                                                   const float* __restrict__ bias,
                                                   float* __restrict__ C) {
    gemm_body<false>(A, W, bias, C);
}

// ---------------------------------------------------------------------------
// Flash attention with tf32 mma (R2-proven, unchanged except att store rounds).
// Block = (b, h, 64 q-rows), 128 threads (4 warps, 16 rows each).
// ---------------------------------------------------------------------------
#define ASTR 68

__global__ __launch_bounds__(128) void attn_tc() {
    extern __shared__ unsigned smem[];
    unsigned* Ks = smem;                // 64*68
    unsigned* Vs = smem + 64 * ASTR;    // 64*68
    unsigned* Ps = smem + 2 * 64 * ASTR;// 64*68 (Q staging, then P tiles)

    const int tid  = threadIdx.x;
    const int warp = tid >> 5, lane = tid & 31;
    const int g = lane >> 2, t = lane & 3;
    const int bh = blockIdx.x;
    const int b = bh >> 4, h = bh & 15;
    const int q0 = blockIdx.y * 64;

    const size_t base = (size_t)b * SS * EE + (size_t)h * HD;

    // ---- stage Q (scaled, tf32) through Ps, then pull A-fragments to regs
    {
        const float* qp = g_q + base + (size_t)q0 * EE;
        #pragma unroll
        for (int i = 0; i < 8; i++) {
            int id = tid + i * 128;           // 1024 float4: 64 rows x 16
            int r = id >> 4, c4 = id & 15;
            float4 v = *(const float4*)(qp + (size_t)r * EE + c4 * 4);
            unsigned* p = &Ps[r * ASTR + c4 * 4];
            p[0] = f2tf(v.x * SCALE); p[1] = f2tf(v.y * SCALE);
            p[2] = f2tf(v.z * SCALE); p[3] = f2tf(v.w * SCALE);
        }
    }
    __syncthreads();

    unsigned qf[8][4];
    {
        int m = warp * 16;
        #pragma unroll
        for (int ks = 0; ks < 8; ks++) {
            qf[ks][0] = Ps[(m + g)     * ASTR + ks * 8 + t];
            qf[ks][1] = Ps[(m + g + 8) * ASTR + ks * 8 + t];
            qf[ks][2] = Ps[(m + g)     * ASTR + ks * 8 + t + 4];
            qf[ks][3] = Ps[(m + g + 8) * ASTR + ks * 8 + t + 4];
        }
    }
    __syncthreads();

    float o[8][4] = {};
    float mrow0 = -1e30f, mrow1 = -1e30f, lrow0 = 0.f, lrow1 = 0.f;

    const float* kp = g_k + base;
    const float* vp = g_v + base;

    for (int kt = 0; kt < SS / 64; kt++) {
        // ---- load K,V tiles (tf32)
        #pragma unroll
        for (int i = 0; i < 8; i++) {
            int id = tid + i * 128; int r = id >> 4, c4 = id & 15;
            size_t go = (size_t)(kt * 64 + r) * EE + c4 * 4;
            float4 kv = *(const float4*)(kp + go);
            float4 vv = *(const float4*)(vp + go);
            unsigned* pk = &Ks[r * ASTR + c4 * 4];
            pk[0] = f2tf(kv.x); pk[1] = f2tf(kv.y); pk[2] = f2tf(kv.z); pk[3] = f2tf(kv.w);
            unsigned* pv = &Vs[r * ASTR + c4 * 4];
            pv[0] = f2tf(vv.x); pv[1] = f2tf(vv.y); pv[2] = f2tf(vv.z); pv[3] = f2tf(vv.w);
        }
        __syncthreads();

        // ---- S = Q @ K^T  (per warp: 16 x 64)
        float s[8][4] = {};
        #pragma unroll
        for (int ks = 0; ks < 8; ks++) {
            #pragma unroll
            for (int ni = 0; ni < 8; ni++) {
                unsigned bf[2];
                int n = ni * 8 + g;                       // kv index
                bf[0] = Ks[n * ASTR + ks * 8 + t];
                bf[1] = Ks[n * ASTR + ks * 8 + t + 4];
                mma_tf32(s[ni], qf[ks], bf);
            }
        }

        // ---- online softmax (rows g and g+8; reduce over the 4 lanes of t)
        float mx0 = -1e30f, mx1 = -1e30f;
        #pragma unroll
        for (int ni = 0; ni < 8; ni++) {
            mx0 = fmaxf(mx0, fmaxf(s[ni][0], s[ni][1]));
            mx1 = fmaxf(mx1, fmaxf(s[ni][2], s[ni][3]));
        }
        mx0 = fmaxf(mx0, __shfl_xor_sync(0xffffffffu, mx0, 1));
        mx0 = fmaxf(mx0, __shfl_xor_sync(0xffffffffu, mx0, 2));
        mx1 = fmaxf(mx1, __shfl_xor_sync(0xffffffffu, mx1, 1));
        mx1 = fmaxf(mx1, __shfl_xor_sync(0xffffffffu, mx1, 2));

        float mn0 = fmaxf(mrow0, mx0), mn1 = fmaxf(mrow1, mx1);
        float c0 = __expf(mrow0 - mn0), c1 = __expf(mrow1 - mn1);
        float sum0 = 0.f, sum1 = 0.f;
        #pragma unroll
        for (int ni = 0; ni < 8; ni++) {
            s[ni][0] = __expf(s[ni][0] - mn0);
            s[ni][1] = __expf(s[ni][1] - mn0);
            s[ni][2] = __expf(s[ni][2] - mn1);
            s[ni][3] = __expf(s[ni][3] - mn1);
            sum0 += s[ni][0] + s[ni][1];
            sum1 += s[ni][2] + s[ni][3];
        }
        sum0 += __shfl_xor_sync(0xffffffffu, sum0, 1);
        sum0 += __shfl_xor_sync(0xffffffffu, sum0, 2);
        sum1 += __shfl_xor_sync(0xffffffffu, sum1, 1);
        sum1 += __shfl_xor_sync(0xffffffffu, sum1, 2);
        lrow0 = lrow0 * c0 + sum0;  mrow0 = mn0;
        lrow1 = lrow1 * c1 + sum1;  mrow1 = mn1;
        #pragma unroll
        for (int ni = 0; ni < 8; ni++) {
            o[ni][0] *= c0; o[ni][1] *= c0;
            o[ni][2] *= c1; o[ni][3] *= c1;
        }

        // ---- write P (tf32) to warp-local rows of Ps
        {
            int m = warp * 16;
            #pragma unroll
            for (int ni = 0; ni < 8; ni++) {
                uint2 w0 = make_uint2(f2tf(s[ni][0]), f2tf(s[ni][1]));
                uint2 w1 = make_uint2(f2tf(s[ni][2]), f2tf(s[ni][3]));
                *(uint2*)&Ps[(m + g)     * ASTR + ni * 8 + 2 * t] = w0;
                *(uint2*)&Ps[(m + g + 8) * ASTR + ni * 8 + 2 * t] = w1;
            }
        }
        __syncwarp();

        // ---- O += P @ V  (A from Ps, B = Vs[j][d])
        {
            int m = warp * 16;
            #pragma unroll
            for (int ks = 0; ks < 8; ks++) {
                unsigned af[4];
                af[0] = Ps[(m + g)     * ASTR + ks * 8 + t];
                af[1] = Ps[(m + g + 8) * ASTR + ks * 8 + t];
                af[2] = Ps[(m + g)     * ASTR + ks * 8 + t + 4];
                af[3] = Ps[(m + g + 8) * ASTR + ks * 8 + t + 4];
                #pragma unroll
                for (int ni = 0; ni < 8; ni++) {
                    unsigned bf[2];
                    int n = ni * 8 + g;                   // d index
                    bf[0] = Vs[(ks * 8 + t)     * ASTR + n];
                    bf[1] = Vs[(ks * 8 + t + 4) * ASTR + n];
                    mma_tf32(o[ni], af, bf);
                }
            }
        }
        __syncthreads();   // Vs/Ks consumed before next tile load
    }

    // ---- normalize, round to tf32 (consumed by cp.async out_gemm), store
    float inv0 = 1.f / lrow0, inv1 = 1.f / lrow1;
    int r0 = q0 + warp * 16 + g;
    #pragma unroll
    for (int ni = 0; ni < 8; ni++) {
        int d = h * HD + ni * 8 + 2 * t;
        float2 w0, w1;
        w0.x = __uint_as_float(f2tf(o[ni][0] * inv0));
        w0.y = __uint_as_float(f2tf(o[ni][1] * inv0));
        w1.x = __uint_as_float(f2tf(o[ni][2] * inv1));
        w1.y = __uint_as_float(f2tf(o[ni][3] * inv1));
        *(float2*)(g_att + (size_t)(b * SS + r0)     * EE + d) = w0;
        *(float2*)(g_att + (size_t)(b * SS + r0 + 8) * EE + d) = w1;
    }
}

// ---------------------------------------------------------------------------
// Launch
// ---------------------------------------------------------------------------
extern "C" void kernel_launch(void* const* d_in, const int* in_sizes, int n_in,
                              void* d_out, int out_size)
{
    const float* query = (const float*)d_in[0];
    const float* key_  = (const float*)d_in[1];
    const float* value = (const float*)d_in[2];
    const float* Wq = (const float*)d_in[3];
    const float* bq = (const float*)d_in[4];
    const float* Wk = (const float*)d_in[5];
    const float* bk = (const float*)d_in[6];
    const float* Wv = (const float*)d_in[7];
    const float* bv = (const float*)d_in[8];
    const float* Wo = (const float*)d_in[9];
    const float* bo = (const float*)d_in[10];
    float* out = (float*)d_out;

    float *q, *k, *v, *att, *xq, *xk, *xv, *wq, *wk, *wv, *wo;
    cudaGetSymbolAddress((void**)&q,   g_q);
    cudaGetSymbolAddress((void**)&k,   g_k);
    cudaGetSymbolAddress((void**)&v,   g_v);
    cudaGetSymbolAddress((void**)&att, g_att);
    cudaGetSymbolAddress((void**)&xq,  g_xq);
    cudaGetSymbolAddress((void**)&xk,  g_xk);
    cudaGetSymbolAddress((void**)&xv,  g_xv);
    cudaGetSymbolAddress((void**)&wq,  g_wq);
    cudaGetSymbolAddress((void**)&wk,  g_wk);
    cudaGetSymbolAddress((void**)&wv,  g_wv);
    cudaGetSymbolAddress((void**)&wo,  g_wo);

    static bool attr_done = false;
    if (!attr_done) {
        cudaFuncSetAttribute(qkv_gemm, cudaFuncAttributeMaxDynamicSharedMemorySize, 3 * STGB);
        cudaFuncSetAttribute(out_gemm, cudaFuncAttributeMaxDynamicSharedMemorySize, 3 * STGB);
        cudaFuncSetAttribute(attn_tc,  cudaFuncAttributeMaxDynamicSharedMemorySize, 3 * 64 * ASTR * 4);
        attr_done = true;
    }

    // 1) prepass: round inputs + weights to tf32
    RoundArgs ra;
    ra.src[0] = query; ra.dst[0] = xq; ra.n4[0] = MTOT * EE / 4;
    ra.src[1] = key_;  ra.dst[1] = xk; ra.n4[1] = MTOT * EE / 4;
    ra.src[2] = value; ra.dst[2] = xv; ra.n4[2] = EE * MTOT / 4;
    ra.src[3] = Wq;    ra.dst[3] = wq; ra.n4[3] = EE * EE / 4;
    ra.src[4] = Wk;    ra.dst[4] = wk; ra.n4[4] = EE * EE / 4;
    ra.src[5] = Wv;    ra.dst[5] = wv; ra.n4[5] = EE * EE / 4;
    ra.src[6] = Wo;    ra.dst[6] = wo; ra.n4[6] = EE * EE / 4;
    tf32_round<<<dim3(1024, 7), 256>>>(ra);

    // 2) QKV projections
    QKVArgs args;
    args.A[0] = xq; args.A[1] = xk; args.A[2] = xv;
    args.W[0] = wq; args.W[1] = wk; args.W[2] = wv;
    args.bias[0] = bq; args.bias[1] = bk; args.bias[2] = bv;
    args.C[0] = q; args.C[1] = k; args.C[2] = v;
    qkv_gemm<<<dim3(EE / 128, MTOT / 128, 3), 256, 3 * STGB>>>(args);

    // 3) attention
    attn_tc<<<dim3(BB * HH, SS / 64), 128, 3 * 64 * ASTR * 4>>>();

    // 4) output projection
    out_gemm<<<dim3(EE / 128, MTOT / 128), 256, 3 * STGB>>>(att, wo, bo, out);
}

// round 7
// speedup vs baseline: 1.7765x; 1.0522x over previous
#include <cuda_runtime.h>
#include <math.h>

#define BB 2
#define SS 2048
#define EE 1024
#define HH 16
#define HD 64
#define MTOT (BB*SS)
#define SCALE 0.125f   // 1/sqrt(64)

// Scratch (allocation-free rule): device globals
__device__ float g_q[MTOT * EE];     // tf32-rounded Q projection
__device__ float g_k[MTOT * EE];
__device__ float g_v[MTOT * EE];
__device__ float g_att[MTOT * EE];   // tf32-rounded attention output
__device__ float g_xq[MTOT * EE];    // tf32-rounded inputs
__device__ float g_xk[MTOT * EE];
__device__ float g_xv[MTOT * EE];
__device__ float g_wq[EE * EE];      // tf32-rounded weights
__device__ float g_wk[EE * EE];
__device__ float g_wv[EE * EE];
__device__ float g_wo[EE * EE];

// ---------------------------------------------------------------------------
// helpers
// ---------------------------------------------------------------------------
__device__ __forceinline__ unsigned f2tf(float f) {
    unsigned r;
    asm("cvt.rna.tf32.f32 %0, %1;" : "=r"(r) : "f"(f));
    return r;
}

__device__ __forceinline__ void mma_tf32(float c[4], const unsigned a[4], const unsigned b[2]) {
    asm volatile(
        "mma.sync.aligned.m16n8k8.row.col.f32.tf32.tf32.f32 "
        "{%0,%1,%2,%3}, {%4,%5,%6,%7}, {%8,%9}, {%0,%1,%2,%3};"
        : "+f"(c[0]), "+f"(c[1]), "+f"(c[2]), "+f"(c[3])
        : "r"(a[0]), "r"(a[1]), "r"(a[2]), "r"(a[3]), "r"(b[0]), "r"(b[1]));
}

__device__ __forceinline__ void cpa16(unsigned dst, const void* src) {
    asm volatile("cp.async.cg.shared.global [%0], [%1], 16;" :: "r"(dst), "l"(src) : "memory");
}
__device__ __forceinline__ void cp_commit() { asm volatile("cp.async.commit_group;" ::: "memory"); }
__device__ __forceinline__ void cp_wait0() { asm volatile("cp.async.wait_group 0;" ::: "memory"); }
__device__ __forceinline__ void cp_wait1() { asm volatile("cp.async.wait_group 1;" ::: "memory"); }
__device__ __forceinline__ void cp_wait2() { asm volatile("cp.async.wait_group 2;" ::: "memory"); }

// ---------------------------------------------------------------------------
// Prepass: round 7 tensors to tf32 copies
// ---------------------------------------------------------------------------
struct RoundArgs {
    const float* src[7];
    float*       dst[7];
    int          n4[7];
};

__global__ __launch_bounds__(256) void tf32_round(RoundArgs a) {
    const int z = blockIdx.y;
    const int n4 = a.n4[z];
    const float4* s = (const float4*)a.src[z];
    float4* d = (float4*)a.dst[z];
    for (int i = blockIdx.x * blockDim.x + threadIdx.x; i < n4;
         i += gridDim.x * blockDim.x) {
        float4 v = s[i];
        v.x = __uint_as_float(f2tf(v.x));
        v.y = __uint_as_float(f2tf(v.y));
        v.z = __uint_as_float(f2tf(v.z));
        v.w = __uint_as_float(f2tf(v.w));
        d[i] = v;
    }
}

// ---------------------------------------------------------------------------
// GEMM: C[M,N] = A[M,K] @ W[N,K]^T + bias   (A, W pre-rounded tf32)
// R2's exact compute loop: CTA 128x128x32, 256 threads (8 warps 2Mx4N),
// warp tile 64x32, GSTR=36 (conflict-free fragment reads).
// Staging via cp.async, 3 stages, one __syncthreads per K-iter.  (R6 WIN)
// ---------------------------------------------------------------------------
#define GSTR 36
#define STGW 9216            // words per stage: A 128*36, B 128*36
#define STGB (STGW * 4)      // bytes per stage

struct QKVArgs {
    const float* A[3];
    const float* W[3];
    const float* bias[3];
    float*       C[3];
};

template<bool RND>
__device__ __forceinline__ void gemm_body(
    const float* __restrict__ A, const float* __restrict__ W,
    const float* __restrict__ bias, float* __restrict__ C)
{
    extern __shared__ unsigned sm[];   // 3 stages x 9216 words = 108 KB
    const unsigned smem_u = (unsigned)__cvta_generic_to_shared(sm);

    const int tid  = threadIdx.x;
    const int warp = tid >> 5, lane = tid & 31;
    const int g = lane >> 2, t = lane & 3;
    const int wm = warp & 1, wn = warp >> 1;     // 2 x 4 warps, warp tile 64x32
    const int bm = blockIdx.y * 128, bn = blockIdx.x * 128;

    // staging constants: thread covers rows m0+32i (i=0..3), k-quad kq (16B)
    const int kq = tid & 7;          // fixed k-quad
    const int m0 = tid >> 3;         // 0..31
    const float* Asrc = A + (size_t)(bm + m0) * EE + kq * 4;
    const float* Wsrc = W + (size_t)(bn + m0) * EE + kq * 4;
    const unsigned dA = smem_u + (m0 * GSTR + kq * 4) * 4;  // + i*4608B + stage*STGB
    const unsigned dB = dA + 4608 * 4;                      // B block at word 4608

    float acc[4][4][4] = {};
    const int NK = EE / 32;          // 32

    // prologue: stage tiles 0 and 1
    #pragma unroll
    for (int p = 0; p < 2; p++) {
        const unsigned so = p * STGB;
        const int ko = p * 32;
        #pragma unroll
        for (int i = 0; i < 4; i++) {
            cpa16(dA + so + i * 4608, Asrc + ko + (size_t)i * 32 * EE);
            cpa16(dB + so + i * 4608, Wsrc + ko + (size_t)i * 32 * EE);
        }
        cp_commit();
    }

    int st = 0;   // stage holding tile kt
    for (int kt = 0; kt < NK; kt++) {
        if (kt + 1 < NK) cp_wait1(); else cp_wait0();
        __syncthreads();

        // prefetch tile kt+2 into stage (st+2)%3 (its readers done at kt-1)
        if (kt + 2 < NK) {
            const int s2 = (st + 2 >= 3) ? st - 1 : st + 2;
            const unsigned so = s2 * STGB;
            const int ko = (kt + 2) * 32;
            #pragma unroll
            for (int i = 0; i < 4; i++) {
                cpa16(dA + so + i * 4608, Asrc + ko + (size_t)i * 32 * EE);
                cpa16(dB + so + i * 4608, Wsrc + ko + (size_t)i * 32 * EE);
            }
            cp_commit();
        }

        // ---- R2 compute loop: 4 k-steps of 8
        const unsigned* Asm = sm + st * STGW;
        const unsigned* Bsm = Asm + 4608;
        #pragma unroll
        for (int ksc = 0; ksc < 4; ksc++) {
            unsigned af[4][4], bf[4][2];
            #pragma unroll
            for (int mi = 0; mi < 4; mi++) {
                const int row = wm * 64 + mi * 16;
                af[mi][0] = Asm[(row + g)     * GSTR + ksc * 8 + t];
                af[mi][1] = Asm[(row + g + 8) * GSTR + ksc * 8 + t];
                af[mi][2] = Asm[(row + g)     * GSTR + ksc * 8 + t + 4];
                af[mi][3] = Asm[(row + g + 8) * GSTR + ksc * 8 + t + 4];
            }
            #pragma unroll
            for (int ni = 0; ni < 4; ni++) {
                const int col = wn * 32 + ni * 8 + g;
                bf[ni][0] = Bsm[col * GSTR + ksc * 8 + t];
                bf[ni][1] = Bsm[col * GSTR + ksc * 8 + t + 4];
            }
            #pragma unroll
            for (int mi = 0; mi < 4; mi++)
                #pragma unroll
                for (int ni = 0; ni < 4; ni++)
                    mma_tf32(acc[mi][ni], af[mi], bf[ni]);
        }
        st = (st + 1 >= 3) ? 0 : st + 1;
    }

    // ---- epilogue: add bias (fp32), optional tf32 round, store
    #pragma unroll
    for (int mi = 0; mi < 4; mi++) {
        #pragma unroll
        for (int r2 = 0; r2 < 2; r2++) {
            const int m = bm + wm * 64 + mi * 16 + g + r2 * 8;
            #pragma unroll
            for (int ni = 0; ni < 4; ni++) {
                const int n = bn + wn * 32 + ni * 8 + 2 * t;
                float2 bv = *(const float2*)(bias + n);
                float2 o;
                o.x = acc[mi][ni][r2 * 2 + 0] + bv.x;
                o.y = acc[mi][ni][r2 * 2 + 1] + bv.y;
                if (RND) {
                    o.x = __uint_as_float(f2tf(o.x));
                    o.y = __uint_as_float(f2tf(o.y));
                }
                *(float2*)(C + (size_t)m * EE + n) = o;
            }
        }
    }
}

__global__ __launch_bounds__(256, 2) void qkv_gemm(QKVArgs args) {
    const int z = blockIdx.z;
    gemm_body<true>(args.A[z], args.W[z], args.bias[z], args.C[z]);
}

__global__ __launch_bounds__(256, 2) void out_gemm(const float* __restrict__ A,
                                                   const float* __restrict__ W,
                                                   const float* __restrict__ bias,
                                                   float* __restrict__ C) {
    gemm_body<false>(A, W, bias, C);
}

// ---------------------------------------------------------------------------
// Flash attention, tf32 mma (R2/R6 layouts), cp.async pipelined staging.
// Block = (b, h, 64 q-rows), 128 threads (4 warps, 16 rows each).
// g_q/g_k/g_v are pre-rounded tf32 -> raw 16B copies, no CVT.
// Pipeline: commit groups Q | K[kt] | V[kt]; K[kt+1] committed during PV wait,
// V[kt+1] committed during next S phase.
// ---------------------------------------------------------------------------
#define ASTR 68

__global__ __launch_bounds__(128) void attn_tc() {
    extern __shared__ unsigned smem[];
    unsigned* Ks = smem;                // 64*68
    unsigned* Vs = smem + 64 * ASTR;    // 64*68
    unsigned* Ps = smem + 2 * 64 * ASTR;// 64*68 (Q staging, then P tiles)
    const unsigned smem_u = (unsigned)__cvta_generic_to_shared(smem);
    const unsigned Ks_u = smem_u;
    const unsigned Vs_u = smem_u + 64 * ASTR * 4;
    const unsigned Ps_u = smem_u + 2 * 64 * ASTR * 4;

    const int tid  = threadIdx.x;
    const int warp = tid >> 5, lane = tid & 31;
    const int g = lane >> 2, t = lane & 3;
    const int bh = blockIdx.x;
    const int b = bh >> 4, h = bh & 15;
    const int q0 = blockIdx.y * 64;

    const size_t base = (size_t)b * SS * EE + (size_t)h * HD;

    // staging thread constants: rows r0 + 8i (i=0..7), 16B chunk c4
    const int r0 = tid >> 4;         // 0..7
    const int c4 = tid & 15;         // 0..15
    const unsigned dstW = (unsigned)((r0 * ASTR + c4 * 4) * 4);  // byte offset, 16B aligned

    const float* qsrc = g_q + base + (size_t)(q0 + r0) * EE + c4 * 4;
    const float* ksrc = g_k + base + (size_t)r0 * EE + c4 * 4;
    const float* vsrc = g_v + base + (size_t)r0 * EE + c4 * 4;

    // ---- prologue: Q -> Ps (group1), K0 -> Ks (group2), V0 -> Vs (group3)
    #pragma unroll
    for (int i = 0; i < 8; i++)
        cpa16(Ps_u + dstW + i * 8 * ASTR * 4, qsrc + (size_t)i * 8 * EE);
    cp_commit();
    #pragma unroll
    for (int i = 0; i < 8; i++)
        cpa16(Ks_u + dstW + i * 8 * ASTR * 4, ksrc + (size_t)i * 8 * EE);
    cp_commit();
    #pragma unroll
    for (int i = 0; i < 8; i++)
        cpa16(Vs_u + dstW + i * 8 * ASTR * 4, vsrc + (size_t)i * 8 * EE);
    cp_commit();

    cp_wait2();          // Q arrived; K0, V0 still pending
    __syncthreads();

    // pull Q A-fragments (warp-local rows), fold SCALE (power of 2: exact)
    unsigned qf[8][4];
    {
        const int m = warp * 16;
        #pragma unroll
        for (int ks = 0; ks < 8; ks++) {
            qf[ks][0] = Ps[(m + g)     * ASTR + ks * 8 + t];
            qf[ks][1] = Ps[(m + g + 8) * ASTR + ks * 8 + t];
            qf[ks][2] = Ps[(m + g)     * ASTR + ks * 8 + t + 4];
            qf[ks][3] = Ps[(m + g + 8) * ASTR + ks * 8 + t + 4];
            #pragma unroll
            for (int j = 0; j < 4; j++)
                qf[ks][j] = __float_as_uint(__uint_as_float(qf[ks][j]) * SCALE);
        }
    }

    float o[8][4] = {};
    float mrow0 = -1e30f, mrow1 = -1e30f, lrow0 = 0.f, lrow1 = 0.f;

    const int NT = SS / 64;
    for (int kt = 0; kt < NT; kt++) {
        // ---- K[kt] ready (V[kt] may still be in flight)
        cp_wait1();
        __syncthreads();

        // ---- S = Q @ K^T  (per warp: 16 x 64)
        float s[8][4] = {};
        #pragma unroll
        for (int ks = 0; ks < 8; ks++) {
            #pragma unroll
            for (int ni = 0; ni < 8; ni++) {
                unsigned bf[2];
                const int n = ni * 8 + g;                 // kv index
                bf[0] = Ks[n * ASTR + ks * 8 + t];
                bf[1] = Ks[n * ASTR + ks * 8 + t + 4];
                mma_tf32(s[ni], qf[ks], bf);
            }
        }

        // ---- online softmax (rows g and g+8; reduce over the 4 lanes of t)
        float mx0 = -1e30f, mx1 = -1e30f;
        #pragma unroll
        for (int ni = 0; ni < 8; ni++) {
            mx0 = fmaxf(mx0, fmaxf(s[ni][0], s[ni][1]));
            mx1 = fmaxf(mx1, fmaxf(s[ni][2], s[ni][3]));
        }
        mx0 = fmaxf(mx0, __shfl_xor_sync(0xffffffffu, mx0, 1));
        mx0 = fmaxf(mx0, __shfl_xor_sync(0xffffffffu, mx0, 2));
        mx1 = fmaxf(mx1, __shfl_xor_sync(0xffffffffu, mx1, 1));
        mx1 = fmaxf(mx1, __shfl_xor_sync(0xffffffffu, mx1, 2));

        float mn0 = fmaxf(mrow0, mx0), mn1 = fmaxf(mrow1, mx1);
        float c0 = __expf(mrow0 - mn0), c1 = __expf(mrow1 - mn1);
        float sum0 = 0.f, sum1 = 0.f;
        #pragma unroll
        for (int ni = 0; ni < 8; ni++) {
            s[ni][0] = __expf(s[ni][0] - mn0);
            s[ni][1] = __expf(s[ni][1] - mn0);
            s[ni][2] = __expf(s[ni][2] - mn1);
            s[ni][3] = __expf(s[ni][3] - mn1);
            sum0 += s[ni][0] + s[ni][1];
            sum1 += s[ni][2] + s[ni][3];
        }
        sum0 += __shfl_xor_sync(0xffffffffu, sum0, 1);
        sum0 += __shfl_xor_sync(0xffffffffu, sum0, 2);
        sum1 += __shfl_xor_sync(0xffffffffu, sum1, 1);
        sum1 += __shfl_xor_sync(0xffffffffu, sum1, 2);
        lrow0 = lrow0 * c0 + sum0;  mrow0 = mn0;
        lrow1 = lrow1 * c1 + sum1;  mrow1 = mn1;
        #pragma unroll
        for (int ni = 0; ni < 8; ni++) {
            o[ni][0] *= c0; o[ni][1] *= c0;
            o[ni][2] *= c1; o[ni][3] *= c1;
        }

        // ---- all warps done reading Ks; prefetch K[kt+1] (overlaps PV)
        __syncthreads();
        if (kt + 1 < NT) {
            const float* kn = ksrc + (size_t)(kt + 1) * 64 * EE;
            #pragma unroll
            for (int i = 0; i < 8; i++)
                cpa16(Ks_u + dstW + i * 8 * ASTR * 4, kn + (size_t)i * 8 * EE);
            cp_commit();
            cp_wait1();   // V[kt] arrived (K[kt+1] still pending)
        } else {
            cp_wait0();   // V[kt] arrived
        }
        __syncthreads();

        // ---- write P (tf32) to warp-local rows of Ps
        {
            const int m = warp * 16;
            #pragma unroll
            for (int ni = 0; ni < 8; ni++) {
                uint2 w0 = make_uint2(f2tf(s[ni][0]), f2tf(s[ni][1]));
                uint2 w1 = make_uint2(f2tf(s[ni][2]), f2tf(s[ni][3]));
                *(uint2*)&Ps[(m + g)     * ASTR + ni * 8 + 2 * t] = w0;
                *(uint2*)&Ps[(m + g + 8) * ASTR + ni * 8 + 2 * t] = w1;
            }
        }
        __syncwarp();

        // ---- O += P @ V  (A from Ps, B = Vs[j][d])
        {
            const int m = warp * 16;
            #pragma unroll
            for (int ks = 0; ks < 8; ks++) {
                unsigned af[4];
                af[0] = Ps[(m + g)     * ASTR + ks * 8 + t];
                af[1] = Ps[(m + g + 8) * ASTR + ks * 8 + t];
                af[2] = Ps[(m + g)     * ASTR + ks * 8 + t + 4];
                af[3] = Ps[(m + g + 8) * ASTR + ks * 8 + t + 4];
                #pragma unroll
                for (int ni = 0; ni < 8; ni++) {
                    unsigned bf[2];
                    const int n = ni * 8 + g;             // d index
                    bf[0] = Vs[(ks * 8 + t)     * ASTR + n];
                    bf[1] = Vs[(ks * 8 + t + 4) * ASTR + n];
                    mma_tf32(o[ni], af, bf);
                }
            }
        }
        __syncthreads();   // all warps done reading Vs

        // ---- prefetch V[kt+1] (overlaps next S phase)
        if (kt + 1 < NT) {
            const float* vn = vsrc + (size_t)(kt + 1) * 64 * EE;
            #pragma unroll
            for (int i = 0; i < 8; i++)
                cpa16(Vs_u + dstW + i * 8 * ASTR * 4, vn + (size_t)i * 8 * EE);
            cp_commit();
        }
    }

    // ---- normalize, round to tf32 (consumed by cp.async out_gemm), store
    float inv0 = 1.f / lrow0, inv1 = 1.f / lrow1;
    const int r0q = q0 + warp * 16 + g;
    #pragma unroll
    for (int ni = 0; ni < 8; ni++) {
        const int d = h * HD + ni * 8 + 2 * t;
        float2 w0, w1;
        w0.x = __uint_as_float(f2tf(o[ni][0] * inv0));
        w0.y = __uint_as_float(f2tf(o[ni][1] * inv0));
        w1.x = __uint_as_float(f2tf(o[ni][2] * inv1));
        w1.y = __uint_as_float(f2tf(o[ni][3] * inv1));
        *(float2*)(g_att + (size_t)(b * SS + r0q)     * EE + d) = w0;
        *(float2*)(g_att + (size_t)(b * SS + r0q + 8) * EE + d) = w1;
    }
}

// ---------------------------------------------------------------------------
// Launch
// ---------------------------------------------------------------------------
extern "C" void kernel_launch(void* const* d_in, const int* in_sizes, int n_in,
                              void* d_out, int out_size)
{
    const float* query = (const float*)d_in[0];
    const float* key_  = (const float*)d_in[1];
    const float* value = (const float*)d_in[2];
    const float* Wq = (const float*)d_in[3];
    const float* bq = (const float*)d_in[4];
    const float* Wk = (const float*)d_in[5];
    const float* bk = (const float*)d_in[6];
    const float* Wv = (const float*)d_in[7];
    const float* bv = (const float*)d_in[8];
    const float* Wo = (const float*)d_in[9];
    const float* bo = (const float*)d_in[10];
    float* out = (float*)d_out;

    float *q, *k, *v, *att, *xq, *xk, *xv, *wq, *wk, *wv, *wo;
    cudaGetSymbolAddress((void**)&q,   g_q);
    cudaGetSymbolAddress((void**)&k,   g_k);
    cudaGetSymbolAddress((void**)&v,   g_v);
    cudaGetSymbolAddress((void**)&att, g_att);
    cudaGetSymbolAddress((void**)&xq,  g_xq);
    cudaGetSymbolAddress((void**)&xk,  g_xk);
    cudaGetSymbolAddress((void**)&xv,  g_xv);
    cudaGetSymbolAddress((void**)&wq,  g_wq);
    cudaGetSymbolAddress((void**)&wk,  g_wk);
    cudaGetSymbolAddress((void**)&wv,  g_wv);
    cudaGetSymbolAddress((void**)&wo,  g_wo);

    static bool attr_done = false;
    if (!attr_done) {
        cudaFuncSetAttribute(qkv_gemm, cudaFuncAttributeMaxDynamicSharedMemorySize, 3 * STGB);
        cudaFuncSetAttribute(out_gemm, cudaFuncAttributeMaxDynamicSharedMemorySize, 3 * STGB);
        cudaFuncSetAttribute(attn_tc,  cudaFuncAttributeMaxDynamicSharedMemorySize, 3 * 64 * ASTR * 4);
        attr_done = true;
    }

    // 1) prepass: round inputs + weights to tf32
    RoundArgs ra;
    ra.src[0] = query; ra.dst[0] = xq; ra.n4[0] = MTOT * EE / 4;
    ra.src[1] = key_;  ra.dst[1] = xk; ra.n4[1] = MTOT * EE / 4;
    ra.src[2] = value; ra.dst[2] = xv; ra.n4[2] = MTOT * EE / 4;
    ra.src[3] = Wq;    ra.dst[3] = wq; ra.n4[3] = EE * EE / 4;
    ra.src[4] = Wk;    ra.dst[4] = wk; ra.n4[4] = EE * EE / 4;
    ra.src[5] = Wv;    ra.dst[5] = wv; ra.n4[5] = EE * EE / 4;
    ra.src[6] = Wo;    ra.dst[6] = wo; ra.n4[6] = EE * EE / 4;
    tf32_round<<<dim3(1024, 7), 256>>>(ra);

    // 2) QKV projections
    QKVArgs args;
    args.A[0] = xq; args.A[1] = xk; args.A[2] = xv;
    args.W[0] = wq; args.W[1] = wk; args.W[2] = wv;
    args.bias[0] = bq; args.bias[1] = bk; args.bias[2] = bv;
    args.C[0] = q; args.C[1] = k; args.C[2] = v;
    qkv_gemm<<<dim3(EE / 128, MTOT / 128, 3), 256, 3 * STGB>>>(args);

    // 3) attention
    attn_tc<<<dim3(BB * HH, SS / 64), 128, 3 * 64 * ASTR * 4>>>();

    // 4) output projection
    out_gemm<<<dim3(EE / 128, MTOT / 128), 256, 3 * STGB>>>(att, wo, bo, out);
}

// round 8
// speedup vs baseline: 1.8107x; 1.0193x over previous
#include <cuda_runtime.h>
#include <math.h>

#define BB 2
#define SS 2048
#define EE 1024
#define HH 16
#define HD 64
#define MTOT (BB*SS)
#define SCALE 0.125f   // 1/sqrt(64)

// Scratch (allocation-free rule): device globals
__device__ float g_q[MTOT * EE];     // tf32-rounded Q projection
__device__ float g_k[MTOT * EE];
__device__ float g_v[MTOT * EE];
__device__ float g_att[MTOT * EE];   // tf32-rounded attention output
__device__ float g_xq[MTOT * EE];    // tf32-rounded inputs
__device__ float g_xk[MTOT * EE];
__device__ float g_xv[MTOT * EE];
__device__ float g_wq[EE * EE];      // tf32-rounded weights
__device__ float g_wk[EE * EE];
__device__ float g_wv[EE * EE];
__device__ float g_wo[EE * EE];

// ---------------------------------------------------------------------------
// helpers
// ---------------------------------------------------------------------------
__device__ __forceinline__ unsigned f2tf(float f) {
    unsigned r;
    asm("cvt.rna.tf32.f32 %0, %1;" : "=r"(r) : "f"(f));
    return r;
}

__device__ __forceinline__ void mma_tf32(float c[4], const unsigned a[4], const unsigned b[2]) {
    asm volatile(
        "mma.sync.aligned.m16n8k8.row.col.f32.tf32.tf32.f32 "
        "{%0,%1,%2,%3}, {%4,%5,%6,%7}, {%8,%9}, {%0,%1,%2,%3};"
        : "+f"(c[0]), "+f"(c[1]), "+f"(c[2]), "+f"(c[3])
        : "r"(a[0]), "r"(a[1]), "r"(a[2]), "r"(a[3]), "r"(b[0]), "r"(b[1]));
}

__device__ __forceinline__ void cpa16(unsigned dst, const void* src) {
    asm volatile("cp.async.cg.shared.global [%0], [%1], 16;" :: "r"(dst), "l"(src) : "memory");
}
__device__ __forceinline__ void cp_commit() { asm volatile("cp.async.commit_group;" ::: "memory"); }
__device__ __forceinline__ void cp_wait0() { asm volatile("cp.async.wait_group 0;" ::: "memory"); }
__device__ __forceinline__ void cp_wait1() { asm volatile("cp.async.wait_group 1;" ::: "memory"); }
__device__ __forceinline__ void cp_wait2() { asm volatile("cp.async.wait_group 2;" ::: "memory"); }

// ---------------------------------------------------------------------------
// Prepass: round 7 tensors to tf32 copies
// ---------------------------------------------------------------------------
struct RoundArgs {
    const float* src[7];
    float*       dst[7];
    int          n4[7];
};

__global__ __launch_bounds__(256) void tf32_round(RoundArgs a) {
    const int z = blockIdx.y;
    const int n4 = a.n4[z];
    const float4* s = (const float4*)a.src[z];
    float4* d = (float4*)a.dst[z];
    for (int i = blockIdx.x * blockDim.x + threadIdx.x; i < n4;
         i += gridDim.x * blockDim.x) {
        float4 v = s[i];
        v.x = __uint_as_float(f2tf(v.x));
        v.y = __uint_as_float(f2tf(v.y));
        v.z = __uint_as_float(f2tf(v.z));
        v.w = __uint_as_float(f2tf(v.w));
        d[i] = v;
    }
}

// ---------------------------------------------------------------------------
// GEMM: C[M,N] = A[M,K] @ W[N,K]^T + bias   (A, W pre-rounded tf32)
// R2's exact compute loop: CTA 128x128x32, 256 threads (8 warps 2Mx4N),
// warp tile 64x32, GSTR=36 (conflict-free fragment reads).
// Staging via cp.async, 3 stages, one __syncthreads per K-iter.  (R6 WIN)
// ---------------------------------------------------------------------------
#define GSTR 36
#define STGW 9216            // words per stage: A 128*36, B 128*36
#define STGB (STGW * 4)      // bytes per stage

struct QKVArgs {
    const float* A[3];
    const float* W[3];
    const float* bias[3];
    float*       C[3];
};

template<bool RND>
__device__ __forceinline__ void gemm_body(
    const float* __restrict__ A, const float* __restrict__ W,
    const float* __restrict__ bias, float* __restrict__ C)
{
    extern __shared__ unsigned sm[];   // 3 stages x 9216 words = 108 KB
    const unsigned smem_u = (unsigned)__cvta_generic_to_shared(sm);

    const int tid  = threadIdx.x;
    const int warp = tid >> 5, lane = tid & 31;
    const int g = lane >> 2, t = lane & 3;
    const int wm = warp & 1, wn = warp >> 1;     // 2 x 4 warps, warp tile 64x32
    const int bm = blockIdx.y * 128, bn = blockIdx.x * 128;

    // staging constants: thread covers rows m0+32i (i=0..3), k-quad kq (16B)
    const int kq = tid & 7;          // fixed k-quad
    const int m0 = tid >> 3;         // 0..31
    const float* Asrc = A + (size_t)(bm + m0) * EE + kq * 4;
    const float* Wsrc = W + (size_t)(bn + m0) * EE + kq * 4;
    const unsigned dA = smem_u + (m0 * GSTR + kq * 4) * 4;  // + i*4608B + stage*STGB
    const unsigned dB = dA + 4608 * 4;                      // B block at word 4608

    float acc[4][4][4] = {};
    const int NK = EE / 32;          // 32

    // prologue: stage tiles 0 and 1
    #pragma unroll
    for (int p = 0; p < 2; p++) {
        const unsigned so = p * STGB;
        const int ko = p * 32;
        #pragma unroll
        for (int i = 0; i < 4; i++) {
            cpa16(dA + so + i * 4608, Asrc + ko + (size_t)i * 32 * EE);
            cpa16(dB + so + i * 4608, Wsrc + ko + (size_t)i * 32 * EE);
        }
        cp_commit();
    }

    int st = 0;   // stage holding tile kt
    for (int kt = 0; kt < NK; kt++) {
        if (kt + 1 < NK) cp_wait1(); else cp_wait0();
        __syncthreads();

        // prefetch tile kt+2 into stage (st+2)%3 (its readers done at kt-1)
        if (kt + 2 < NK) {
            const int s2 = (st + 2 >= 3) ? st - 1 : st + 2;
            const unsigned so = s2 * STGB;
            const int ko = (kt + 2) * 32;
            #pragma unroll
            for (int i = 0; i < 4; i++) {
                cpa16(dA + so + i * 4608, Asrc + ko + (size_t)i * 32 * EE);
                cpa16(dB + so + i * 4608, Wsrc + ko + (size_t)i * 32 * EE);
            }
            cp_commit();
        }

        // ---- R2 compute loop: 4 k-steps of 8
        const unsigned* Asm = sm + st * STGW;
        const unsigned* Bsm = Asm + 4608;
        #pragma unroll
        for (int ksc = 0; ksc < 4; ksc++) {
            unsigned af[4][4], bf[4][2];
            #pragma unroll
            for (int mi = 0; mi < 4; mi++) {
                const int row = wm * 64 + mi * 16;
                af[mi][0] = Asm[(row + g)     * GSTR + ksc * 8 + t];
                af[mi][1] = Asm[(row + g + 8) * GSTR + ksc * 8 + t];
                af[mi][2] = Asm[(row + g)     * GSTR + ksc * 8 + t + 4];
                af[mi][3] = Asm[(row + g + 8) * GSTR + ksc * 8 + t + 4];
            }
            #pragma unroll
            for (int ni = 0; ni < 4; ni++) {
                const int col = wn * 32 + ni * 8 + g;
                bf[ni][0] = Bsm[col * GSTR + ksc * 8 + t];
                bf[ni][1] = Bsm[col * GSTR + ksc * 8 + t + 4];
            }
            #pragma unroll
            for (int mi = 0; mi < 4; mi++)
                #pragma unroll
                for (int ni = 0; ni < 4; ni++)
                    mma_tf32(acc[mi][ni], af[mi], bf[ni]);
        }
        st = (st + 1 >= 3) ? 0 : st + 1;
    }

    // ---- epilogue: add bias (fp32), optional tf32 round, store
    #pragma unroll
    for (int mi = 0; mi < 4; mi++) {
        #pragma unroll
        for (int r2 = 0; r2 < 2; r2++) {
            const int m = bm + wm * 64 + mi * 16 + g + r2 * 8;
            #pragma unroll
            for (int ni = 0; ni < 4; ni++) {
                const int n = bn + wn * 32 + ni * 8 + 2 * t;
                float2 bv = *(const float2*)(bias + n);
                float2 o;
                o.x = acc[mi][ni][r2 * 2 + 0] + bv.x;
                o.y = acc[mi][ni][r2 * 2 + 1] + bv.y;
                if (RND) {
                    o.x = __uint_as_float(f2tf(o.x));
                    o.y = __uint_as_float(f2tf(o.y));
                }
                *(float2*)(C + (size_t)m * EE + n) = o;
            }
        }
    }
}

__global__ __launch_bounds__(256, 2) void qkv_gemm(QKVArgs args) {
    const int z = blockIdx.z;
    gemm_body<true>(args.A[z], args.W[z], args.bias[z], args.C[z]);
}

__global__ __launch_bounds__(256, 2) void out_gemm(const float* __restrict__ A,
                                                   const float* __restrict__ W,
                                                   const float* __restrict__ bias,
                                                   float* __restrict__ C) {
    gemm_body<false>(A, W, bias, C);
}

// ---------------------------------------------------------------------------
// Flash attention, tf32 mma (R2/R6 layouts), cp.async pipelined staging (R7).
// Block = (b, h, 64 q-rows), 128 threads (4 warps, 16 rows each).
// R8: __launch_bounds__(128, 4) -> 4 CTAs/SM (16 warps) if regs fit 128.
// ---------------------------------------------------------------------------
#define ASTR 68

__global__ __launch_bounds__(128, 4) void attn_tc() {
    extern __shared__ unsigned smem[];
    unsigned* Ks = smem;                // 64*68
    unsigned* Vs = smem + 64 * ASTR;    // 64*68
    unsigned* Ps = smem + 2 * 64 * ASTR;// 64*68 (Q staging, then P tiles)
    const unsigned smem_u = (unsigned)__cvta_generic_to_shared(smem);
    const unsigned Ks_u = smem_u;
    const unsigned Vs_u = smem_u + 64 * ASTR * 4;
    const unsigned Ps_u = smem_u + 2 * 64 * ASTR * 4;

    const int tid  = threadIdx.x;
    const int warp = tid >> 5, lane = tid & 31;
    const int g = lane >> 2, t = lane & 3;
    const int bh = blockIdx.x;
    const int b = bh >> 4, h = bh & 15;
    const int q0 = blockIdx.y * 64;

    const size_t base = (size_t)b * SS * EE + (size_t)h * HD;

    // staging thread constants: rows r0 + 8i (i=0..7), 16B chunk c4
    const int r0 = tid >> 4;         // 0..7
    const int c4 = tid & 15;         // 0..15
    const unsigned dstW = (unsigned)((r0 * ASTR + c4 * 4) * 4);  // byte offset, 16B aligned

    const float* qsrc = g_q + base + (size_t)(q0 + r0) * EE + c4 * 4;
    const float* ksrc = g_k + base + (size_t)r0 * EE + c4 * 4;
    const float* vsrc = g_v + base + (size_t)r0 * EE + c4 * 4;

    // ---- prologue: Q -> Ps (group1), K0 -> Ks (group2), V0 -> Vs (group3)
    #pragma unroll
    for (int i = 0; i < 8; i++)
        cpa16(Ps_u + dstW + i * 8 * ASTR * 4, qsrc + (size_t)i * 8 * EE);
    cp_commit();
    #pragma unroll
    for (int i = 0; i < 8; i++)
        cpa16(Ks_u + dstW + i * 8 * ASTR * 4, ksrc + (size_t)i * 8 * EE);
    cp_commit();
    #pragma unroll
    for (int i = 0; i < 8; i++)
        cpa16(Vs_u + dstW + i * 8 * ASTR * 4, vsrc + (size_t)i * 8 * EE);
    cp_commit();

    cp_wait2();          // Q arrived; K0, V0 still pending
    __syncthreads();

    // pull Q A-fragments (warp-local rows), fold SCALE (power of 2: exact)
    unsigned qf[8][4];
    {
        const int m = warp * 16;
        #pragma unroll
        for (int ks = 0; ks < 8; ks++) {
            qf[ks][0] = Ps[(m + g)     * ASTR + ks * 8 + t];
            qf[ks][1] = Ps[(m + g + 8) * ASTR + ks * 8 + t];
            qf[ks][2] = Ps[(m + g)     * ASTR + ks * 8 + t + 4];
            qf[ks][3] = Ps[(m + g + 8) * ASTR + ks * 8 + t + 4];
            #pragma unroll
            for (int j = 0; j < 4; j++)
                qf[ks][j] = __float_as_uint(__uint_as_float(qf[ks][j]) * SCALE);
        }
    }

    float o[8][4] = {};
    float mrow0 = -1e30f, mrow1 = -1e30f, lrow0 = 0.f, lrow1 = 0.f;

    const int NT = SS / 64;
    for (int kt = 0; kt < NT; kt++) {
        // ---- K[kt] ready (V[kt] may still be in flight)
        cp_wait1();
        __syncthreads();

        // ---- S = Q @ K^T  (per warp: 16 x 64)
        float s[8][4] = {};
        #pragma unroll
        for (int ks = 0; ks < 8; ks++) {
            #pragma unroll
            for (int ni = 0; ni < 8; ni++) {
                unsigned bf[2];
                const int n = ni * 8 + g;                 // kv index
                bf[0] = Ks[n * ASTR + ks * 8 + t];
                bf[1] = Ks[n * ASTR + ks * 8 + t + 4];
                mma_tf32(s[ni], qf[ks], bf);
            }
        }

        // ---- online softmax (rows g and g+8; reduce over the 4 lanes of t)
        float mx0 = -1e30f, mx1 = -1e30f;
        #pragma unroll
        for (int ni = 0; ni < 8; ni++) {
            mx0 = fmaxf(mx0, fmaxf(s[ni][0], s[ni][1]));
            mx1 = fmaxf(mx1, fmaxf(s[ni][2], s[ni][3]));
        }
        mx0 = fmaxf(mx0, __shfl_xor_sync(0xffffffffu, mx0, 1));
        mx0 = fmaxf(mx0, __shfl_xor_sync(0xffffffffu, mx0, 2));
        mx1 = fmaxf(mx1, __shfl_xor_sync(0xffffffffu, mx1, 1));
        mx1 = fmaxf(mx1, __shfl_xor_sync(0xffffffffu, mx1, 2));

        float mn0 = fmaxf(mrow0, mx0), mn1 = fmaxf(mrow1, mx1);
        float c0 = __expf(mrow0 - mn0), c1 = __expf(mrow1 - mn1);
        float sum0 = 0.f, sum1 = 0.f;
        #pragma unroll
        for (int ni = 0; ni < 8; ni++) {
            s[ni][0] = __expf(s[ni][0] - mn0);
            s[ni][1] = __expf(s[ni][1] - mn0);
            s[ni][2] = __expf(s[ni][2] - mn1);
            s[ni][3] = __expf(s[ni][3] - mn1);
            sum0 += s[ni][0] + s[ni][1];
            sum1 += s[ni][2] + s[ni][3];
        }
        sum0 += __shfl_xor_sync(0xffffffffu, sum0, 1);
        sum0 += __shfl_xor_sync(0xffffffffu, sum0, 2);
        sum1 += __shfl_xor_sync(0xffffffffu, sum1, 1);
        sum1 += __shfl_xor_sync(0xffffffffu, sum1, 2);
        lrow0 = lrow0 * c0 + sum0;  mrow0 = mn0;
        lrow1 = lrow1 * c1 + sum1;  mrow1 = mn1;
        #pragma unroll
        for (int ni = 0; ni < 8; ni++) {
            o[ni][0] *= c0; o[ni][1] *= c0;
            o[ni][2] *= c1; o[ni][3] *= c1;
        }

        // ---- all warps done reading Ks; prefetch K[kt+1] (overlaps PV)
        __syncthreads();
        if (kt + 1 < NT) {
            const float* kn = ksrc + (size_t)(kt + 1) * 64 * EE;
            #pragma unroll
            for (int i = 0; i < 8; i++)
                cpa16(Ks_u + dstW + i * 8 * ASTR * 4, kn + (size_t)i * 8 * EE);
            cp_commit();
            cp_wait1();   // V[kt] arrived (K[kt+1] still pending)
        } else {
            cp_wait0();   // V[kt] arrived
        }
        __syncthreads();

        // ---- write P (tf32) to warp-local rows of Ps
        {
            const int m = warp * 16;
            #pragma unroll
            for (int ni = 0; ni < 8; ni++) {
                uint2 w0 = make_uint2(f2tf(s[ni][0]), f2tf(s[ni][1]));
                uint2 w1 = make_uint2(f2tf(s[ni][2]), f2tf(s[ni][3]));
                *(uint2*)&Ps[(m + g)     * ASTR + ni * 8 + 2 * t] = w0;
                *(uint2*)&Ps[(m + g + 8) * ASTR + ni * 8 + 2 * t] = w1;
            }
        }
        __syncwarp();

        // ---- O += P @ V  (A from Ps, B = Vs[j][d])
        {
            const int m = warp * 16;
            #pragma unroll
            for (int ks = 0; ks < 8; ks++) {
                unsigned af[4];
                af[0] = Ps[(m + g)     * ASTR + ks * 8 + t];
                af[1] = Ps[(m + g + 8) * ASTR + ks * 8 + t];
                af[2] = Ps[(m + g)     * ASTR + ks * 8 + t + 4];
                af[3] = Ps[(m + g + 8) * ASTR + ks * 8 + t + 4];
                #pragma unroll
                for (int ni = 0; ni < 8; ni++) {
                    unsigned bf[2];
                    const int n = ni * 8 + g;             // d index
                    bf[0] = Vs[(ks * 8 + t)     * ASTR + n];
                    bf[1] = Vs[(ks * 8 + t + 4) * ASTR + n];
                    mma_tf32(o[ni], af, bf);
                }
            }
        }
        __syncthreads();   // all warps done reading Vs

        // ---- prefetch V[kt+1] (overlaps next S phase)
        if (kt + 1 < NT) {
            const float* vn = vsrc + (size_t)(kt + 1) * 64 * EE;
            #pragma unroll
            for (int i = 0; i < 8; i++)
                cpa16(Vs_u + dstW + i * 8 * ASTR * 4, vn + (size_t)i * 8 * EE);
            cp_commit();
        }
    }

    // ---- normalize, round to tf32 (consumed by cp.async out_gemm), store
    float inv0 = 1.f / lrow0, inv1 = 1.f / lrow1;
    const int r0q = q0 + warp * 16 + g;
    #pragma unroll
    for (int ni = 0; ni < 8; ni++) {
        const int d = h * HD + ni * 8 + 2 * t;
        float2 w0, w1;
        w0.x = __uint_as_float(f2tf(o[ni][0] * inv0));
        w0.y = __uint_as_float(f2tf(o[ni][1] * inv0));
        w1.x = __uint_as_float(f2tf(o[ni][2] * inv1));
        w1.y = __uint_as_float(f2tf(o[ni][3] * inv1));
        *(float2*)(g_att + (size_t)(b * SS + r0q)     * EE + d) = w0;
        *(float2*)(g_att + (size_t)(b * SS + r0q + 8) * EE + d) = w1;
    }
}

// ---------------------------------------------------------------------------
// Launch
// ---------------------------------------------------------------------------
extern "C" void kernel_launch(void* const* d_in, const int* in_sizes, int n_in,
                              void* d_out, int out_size)
{
    const float* query = (const float*)d_in[0];
    const float* key_  = (const float*)d_in[1];
    const float* value = (const float*)d_in[2];
    const float* Wq = (const float*)d_in[3];
    const float* bq = (const float*)d_in[4];
    const float* Wk = (const float*)d_in[5];
    const float* bk = (const float*)d_in[6];
    const float* Wv = (const float*)d_in[7];
    const float* bv = (const float*)d_in[8];
    const float* Wo = (const float*)d_in[9];
    const float* bo = (const float*)d_in[10];
    float* out = (float*)d_out;

    float *q, *k, *v, *att, *xq, *xk, *xv, *wq, *wk, *wv, *wo;
    cudaGetSymbolAddress((void**)&q,   g_q);
    cudaGetSymbolAddress((void**)&k,   g_k);
    cudaGetSymbolAddress((void**)&v,   g_v);
    cudaGetSymbolAddress((void**)&att, g_att);
    cudaGetSymbolAddress((void**)&xq,  g_xq);
    cudaGetSymbolAddress((void**)&xk,  g_xk);
    cudaGetSymbolAddress((void**)&xv,  g_xv);
    cudaGetSymbolAddress((void**)&wq,  g_wq);
    cudaGetSymbolAddress((void**)&wk,  g_wk);
    cudaGetSymbolAddress((void**)&wv,  g_wv);
    cudaGetSymbolAddress((void**)&wo,  g_wo);

    static bool attr_done = false;
    if (!attr_done) {
        cudaFuncSetAttribute(qkv_gemm, cudaFuncAttributeMaxDynamicSharedMemorySize, 3 * STGB);
        cudaFuncSetAttribute(out_gemm, cudaFuncAttributeMaxDynamicSharedMemorySize, 3 * STGB);
        cudaFuncSetAttribute(attn_tc,  cudaFuncAttributeMaxDynamicSharedMemorySize, 3 * 64 * ASTR * 4);
        attr_done = true;
    }

    // 1) prepass: round inputs + weights to tf32
    RoundArgs ra;
    ra.src[0] = query; ra.dst[0] = xq; ra.n4[0] = MTOT * EE / 4;
    ra.src[1] = key_;  ra.dst[1] = xk; ra.n4[1] = MTOT * EE / 4;
    ra.src[2] = value; ra.dst[2] = xv; ra.n4[2] = MTOT * EE / 4;
    ra.src[3] = Wq;    ra.dst[3] = wq; ra.n4[3] = EE * EE / 4;
    ra.src[4] = Wk;    ra.dst[4] = wk; ra.n4[4] = EE * EE / 4;
    ra.src[5] = Wv;    ra.dst[5] = wv; ra.n4[5] = EE * EE / 4;
    ra.src[6] = Wo;    ra.dst[6] = wo; ra.n4[6] = EE * EE / 4;
    tf32_round<<<dim3(1024, 7), 256>>>(ra);

    // 2) QKV projections
    QKVArgs args;
    args.A[0] = xq; args.A[1] = xk; args.A[2] = xv;
    args.W[0] = wq; args.W[1] = wk; args.W[2] = wv;
    args.bias[0] = bq; args.bias[1] = bk; args.bias[2] = bv;
    args.C[0] = q; args.C[1] = k; args.C[2] = v;
    qkv_gemm<<<dim3(EE / 128, MTOT / 128, 3), 256, 3 * STGB>>>(args);

    // 3) attention
    attn_tc<<<dim3(BB * HH, SS / 64), 128, 3 * 64 * ASTR * 4>>>();

    // 4) output projection
    out_gemm<<<dim3(EE / 128, MTOT / 128), 256, 3 * STGB>>>(att, wo, bo, out);
}